// round 3
// baseline (speedup 1.0000x reference)
#include <cuda_runtime.h>
#include <cuda_bf16.h>
#include <math.h>

#define T_DIM 4096
#define D_DIM 1024
#define NH    16
#define HD    64
#define L_ROT 32

// Scratch (no allocations allowed -> __device__ globals)
__device__ float g_Q[NH * T_DIM * HD];
__device__ float g_K[NH * T_DIM * HD];
__device__ float g_V[NH * T_DIM * HD];
__device__ float g_vals[T_DIM * D_DIM];

// ---------------------------------------------------------------------------
// SGEMM: C = A (MxK, row-major) * B^T  (B is NxK row-major)
// mode 0: C[m*N + n]        (row-major output)
// mode 1: C[((n>>6)*M + m)*64 + (n&63)]   (per-head [h][t][dk] layout)
// BM=BN=128, BK=16, 256 threads, 8x8 micro-tile
// ---------------------------------------------------------------------------
__global__ __launch_bounds__(256) void sgemm_bt(
    const float* __restrict__ A, const float* __restrict__ B,
    float* __restrict__ C, int M, int N, int K, int mode)
{
    __shared__ float As[16][128];
    __shared__ float Bs[16][128];

    const int tid = threadIdx.x;
    const int bm = blockIdx.y * 128;
    const int bn = blockIdx.x * 128;
    const int tx = tid & 15;        // 0..15
    const int ty = tid >> 4;        // 0..15

    const int lr = tid >> 2;        // 0..63
    const int lc = (tid & 3) * 4;   // 0,4,8,12

    float acc[8][8];
#pragma unroll
    for (int i = 0; i < 8; i++)
#pragma unroll
        for (int j = 0; j < 8; j++) acc[i][j] = 0.f;

    for (int k0 = 0; k0 < K; k0 += 16) {
        float4 a0 = *(const float4*)&A[(size_t)(bm + lr) * K + k0 + lc];
        float4 a1 = *(const float4*)&A[(size_t)(bm + lr + 64) * K + k0 + lc];
        float4 b0 = *(const float4*)&B[(size_t)(bn + lr) * K + k0 + lc];
        float4 b1 = *(const float4*)&B[(size_t)(bn + lr + 64) * K + k0 + lc];
        __syncthreads();
        As[lc + 0][lr] = a0.x; As[lc + 1][lr] = a0.y;
        As[lc + 2][lr] = a0.z; As[lc + 3][lr] = a0.w;
        As[lc + 0][lr + 64] = a1.x; As[lc + 1][lr + 64] = a1.y;
        As[lc + 2][lr + 64] = a1.z; As[lc + 3][lr + 64] = a1.w;
        Bs[lc + 0][lr] = b0.x; Bs[lc + 1][lr] = b0.y;
        Bs[lc + 2][lr] = b0.z; Bs[lc + 3][lr] = b0.w;
        Bs[lc + 0][lr + 64] = b1.x; Bs[lc + 1][lr + 64] = b1.y;
        Bs[lc + 2][lr + 64] = b1.z; Bs[lc + 3][lr + 64] = b1.w;
        __syncthreads();

#pragma unroll
        for (int kk = 0; kk < 16; kk++) {
            float a[8], b[8];
#pragma unroll
            for (int i = 0; i < 8; i++) a[i] = As[kk][ty * 8 + i];
#pragma unroll
            for (int j = 0; j < 8; j++) b[j] = Bs[kk][tx * 8 + j];
#pragma unroll
            for (int i = 0; i < 8; i++)
#pragma unroll
                for (int j = 0; j < 8; j++) acc[i][j] += a[i] * b[j];
        }
    }

#pragma unroll
    for (int i = 0; i < 8; i++) {
        int m = bm + ty * 8 + i;
#pragma unroll
        for (int j = 0; j < 8; j++) {
            int n = bn + tx * 8 + j;
            if (mode == 0) {
                C[(size_t)m * N + n] = acc[i][j];
            } else {
                C[(size_t)((n >> 6) * M + m) * 64 + (n & 63)] = acc[i][j];
            }
        }
    }
}

// ---------------------------------------------------------------------------
// RoPE over first 32 dims of each head; one thread per (h, t, pair<16)
// out[p]    = x[p]*cos(f[p])    - x[p+16]*sin(f[p])
// out[p+16] = x[p+16]*cos(f[p+16]) + x[p]*sin(f[p+16])
// ---------------------------------------------------------------------------
__global__ void rope_kernel(float* __restrict__ buf, const float* __restrict__ freqs)
{
    int idx = blockIdx.x * blockDim.x + threadIdx.x;  // NH*T_DIM*16 total
    int p = idx & 15;
    int t = (idx >> 4) & (T_DIM - 1);
    int h = idx >> 16;  // 16*4096 = 65536 per head
    if (h >= NH) return;
    float* x = buf + ((size_t)h * T_DIM + t) * HD;
    float a = x[p];
    float b = x[p + 16];
    float f0 = freqs[t * L_ROT + p];
    float f1 = freqs[t * L_ROT + p + 16];
    x[p]      = a * cosf(f0) - b * sinf(f0);
    x[p + 16] = b * cosf(f1) + a * sinf(f1);
}

// ---------------------------------------------------------------------------
// Causal flash attention per head. Block = 64 threads = 64 query rows.
// Each thread owns one query row: Q row + O accum in registers.
// K/V tiles in SMEM (uniform-address broadcast reads -> conflict-free).
// S staged in SMEM transposed [j][lane] -> conflict-free per-lane column.
// ---------------------------------------------------------------------------
__global__ __launch_bounds__(64) void attn_kernel(
    const float* __restrict__ Qb, const float* __restrict__ Kb,
    const float* __restrict__ Vb, float* __restrict__ vals)
{
    __shared__ float Ks[64][64];
    __shared__ float Vs[64][64];
    __shared__ float Ss[64][64];   // [j][lane]

    const int h = blockIdx.y;
    const int it = blockIdx.x;
    const int r = threadIdx.x;
    const int qi = it * 64 + r;

    // Q row -> registers
    float qreg[64];
    {
        const float* Qh = Qb + ((size_t)h * T_DIM + qi) * HD;
#pragma unroll
        for (int d4 = 0; d4 < 16; d4++) {
            float4 v = ((const float4*)Qh)[d4];
            qreg[4 * d4 + 0] = v.x; qreg[4 * d4 + 1] = v.y;
            qreg[4 * d4 + 2] = v.z; qreg[4 * d4 + 3] = v.w;
        }
    }

    float O[64];
#pragma unroll
    for (int c = 0; c < 64; c++) O[c] = 0.f;
    float m = -INFINITY, l = 0.f;

    const float* Kh = Kb + (size_t)h * T_DIM * HD;
    const float* Vh = Vb + (size_t)h * T_DIM * HD;

    for (int jt = 0; jt <= it; jt++) {
        __syncthreads();
        // cooperative load of K/V tiles (float4, perfectly coalesced)
        for (int i = threadIdx.x; i < 64 * 16; i += 64) {
            int row = i >> 4, c4 = i & 15;
            ((float4*)Ks[row])[c4] = ((const float4*)(Kh + (size_t)(jt * 64 + row) * HD))[c4];
            ((float4*)Vs[row])[c4] = ((const float4*)(Vh + (size_t)(jt * 64 + row) * HD))[c4];
        }
        __syncthreads();

        const int jmax = (jt == it) ? r : 63;

        // S = Q K^T / 8, per-lane row; track row max over valid j
        float rowmax = -INFINITY;
        for (int j = 0; j < 64; j++) {
            float acc = 0.f;
#pragma unroll
            for (int d4 = 0; d4 < 16; d4++) {
                float4 k4 = ((const float4*)Ks[j])[d4];
                acc += qreg[4 * d4 + 0] * k4.x + qreg[4 * d4 + 1] * k4.y
                     + qreg[4 * d4 + 2] * k4.z + qreg[4 * d4 + 3] * k4.w;
            }
            acc *= 0.125f;
            Ss[j][r] = acc;
            if (j <= jmax) rowmax = fmaxf(rowmax, acc);
        }

        float mnew = fmaxf(m, rowmax);
        float corr = __expf(m - mnew);
#pragma unroll
        for (int c = 0; c < 64; c++) O[c] *= corr;

        float psum = 0.f;
        for (int j = 0; j < 64; j++) {
            float sv = Ss[j][r];
            float p = (j <= jmax) ? __expf(sv - mnew) : 0.f;
            psum += p;
#pragma unroll
            for (int c4 = 0; c4 < 16; c4++) {
                float4 v4 = ((const float4*)Vs[j])[c4];
                O[4 * c4 + 0] += p * v4.x; O[4 * c4 + 1] += p * v4.y;
                O[4 * c4 + 2] += p * v4.z; O[4 * c4 + 3] += p * v4.w;
            }
        }
        l = l * corr + psum;
        m = mnew;
    }

    float inv = 1.f / l;
    float* outp = vals + (size_t)qi * D_DIM + h * HD;
#pragma unroll
    for (int c4 = 0; c4 < 16; c4++) {
        float4 o4;
        o4.x = O[4 * c4 + 0] * inv; o4.y = O[4 * c4 + 1] * inv;
        o4.z = O[4 * c4 + 2] * inv; o4.w = O[4 * c4 + 3] * inv;
        ((float4*)outp)[c4] = o4;
    }
}

// ---------------------------------------------------------------------------
extern "C" void kernel_launch(void* const* d_in, const int* in_sizes, int n_in,
                              void* d_out, int out_size)
{
    const float* q     = (const float*)d_in[0];
    const float* k     = (const float*)d_in[1];
    const float* v     = (const float*)d_in[2];
    // d_in[3] = mask (causal, known statically -> unused)
    const float* freqs = (const float*)d_in[4];
    const float* wq    = (const float*)d_in[5];
    const float* wk    = (const float*)d_in[6];
    const float* wv    = (const float*)d_in[7];
    const float* wo    = (const float*)d_in[8];
    float* out = (float*)d_out;

    float *gq, *gk, *gv, *gvals;
    cudaGetSymbolAddress((void**)&gq, g_Q);
    cudaGetSymbolAddress((void**)&gk, g_K);
    cudaGetSymbolAddress((void**)&gv, g_V);
    cudaGetSymbolAddress((void**)&gvals, g_vals);

    dim3 ggrid(D_DIM / 128, T_DIM / 128);  // (8, 32)

    sgemm_bt<<<ggrid, 256>>>(q, wq, gq, T_DIM, D_DIM, D_DIM, 1);
    sgemm_bt<<<ggrid, 256>>>(k, wk, gk, T_DIM, D_DIM, D_DIM, 1);
    sgemm_bt<<<ggrid, 256>>>(v, wv, gv, T_DIM, D_DIM, D_DIM, 1);

    int rope_threads = NH * T_DIM * 16;  // 1,048,576
    rope_kernel<<<rope_threads / 256, 256>>>(gq, freqs);
    rope_kernel<<<rope_threads / 256, 256>>>(gk, freqs);
    rope_kernel<<<rope_threads / 256, 256>>>(gv, freqs);

    attn_kernel<<<dim3(T_DIM / 64, NH), 64>>>(gq, gk, gv, gvals);

    sgemm_bt<<<ggrid, 256>>>(gvals, wo, out, T_DIM, D_DIM, D_DIM, 0);
}

// round 4
// speedup vs baseline: 2.8522x; 2.8522x over previous
#include <cuda_runtime.h>
#include <math.h>

#define T_DIM 4096
#define D_DIM 1024
#define NH    16
#define HD    64
#define L_ROT 32

// Scratch (no allocations allowed -> __device__ globals)
__device__ float g_Q[NH * T_DIM * HD];
__device__ float g_K[NH * T_DIM * HD];
__device__ float g_V[NH * T_DIM * HD];
__device__ float g_vals[T_DIM * D_DIM];

// ---------------------------------------------------------------------------
// tf32 helpers
// ---------------------------------------------------------------------------
__device__ __forceinline__ unsigned f2tf(float f) {
    unsigned u;
    asm("cvt.rna.tf32.f32 %0, %1;" : "=r"(u) : "f"(f));
    return u;
}

// D += A(16x8, row) * B(8x8, col);  tf32 in, f32 accum
__device__ __forceinline__ void mma8(float* d, const unsigned* a, unsigned b0, unsigned b1) {
    asm volatile(
        "mma.sync.aligned.m16n8k8.row.col.f32.tf32.tf32.f32 "
        "{%0,%1,%2,%3}, {%4,%5,%6,%7}, {%8,%9}, {%0,%1,%2,%3};"
        : "+f"(d[0]), "+f"(d[1]), "+f"(d[2]), "+f"(d[3])
        : "r"(a[0]), "r"(a[1]), "r"(a[2]), "r"(a[3]), "r"(b0), "r"(b1));
}

// ---------------------------------------------------------------------------
// tf32 GEMM: C = A (MxK row-major) * B^T (B is NxK row-major)
// mode 0: C[m*N + n] ; mode 1: C[((n>>6)*M + m)*64 + (n&63)]  (per-head layout)
// BM=BN=128, BK=32, 256 threads, warp grid 2(M)x4(N), warp tile 64x32
// ---------------------------------------------------------------------------
__global__ __launch_bounds__(256) void gemm_tf32(
    const float* __restrict__ A, const float* __restrict__ B,
    float* __restrict__ C, int M, int N, int K, int mode)
{
    __shared__ float As[128][36];   // [m][k], pad 36: bank=(4m+k)%32 conflict-free frags
    __shared__ float Bs[128][36];   // [n][k]

    const int tid = threadIdx.x;
    const int bm = blockIdx.y * 128;
    const int bn = blockIdx.x * 128;
    const int w = tid >> 5, lane = tid & 31;
    const int g = lane >> 2, tg = lane & 3;
    const int wm = (w >> 2) * 64;   // warp M offset (0 or 64)
    const int wn = (w & 3) * 32;    // warp N offset (0..96)

    float cf[4][4][4];
#pragma unroll
    for (int mt = 0; mt < 4; mt++)
#pragma unroll
        for (int nt = 0; nt < 4; nt++)
#pragma unroll
            for (int r = 0; r < 4; r++) cf[mt][nt][r] = 0.f;

    const int lm = tid >> 3;        // 0..31 (row within 32-row chunk)
    const int lk4 = tid & 7;        // 0..7  (float4 index within 32-col row)

    for (int k0 = 0; k0 < K; k0 += 32) {
        float4 av[4], bv[4];
#pragma unroll
        for (int p = 0; p < 4; p++) {
            int m = lm + p * 32;
            av[p] = *(const float4*)&A[(size_t)(bm + m) * K + k0 + 4 * lk4];
            bv[p] = *(const float4*)&B[(size_t)(bn + m) * K + k0 + 4 * lk4];
        }
        __syncthreads();
#pragma unroll
        for (int p = 0; p < 4; p++) {
            int m = lm + p * 32;
            float4 a = av[p], b = bv[p];
            float4 at = make_float4(__uint_as_float(f2tf(a.x)), __uint_as_float(f2tf(a.y)),
                                    __uint_as_float(f2tf(a.z)), __uint_as_float(f2tf(a.w)));
            float4 bt = make_float4(__uint_as_float(f2tf(b.x)), __uint_as_float(f2tf(b.y)),
                                    __uint_as_float(f2tf(b.z)), __uint_as_float(f2tf(b.w)));
            *(float4*)&As[m][4 * lk4] = at;
            *(float4*)&Bs[m][4 * lk4] = bt;
        }
        __syncthreads();

#pragma unroll
        for (int s = 0; s < 4; s++) {
            unsigned af[4][4];
#pragma unroll
            for (int mt = 0; mt < 4; mt++) {
                int r = wm + mt * 16;
                af[mt][0] = __float_as_uint(As[r + g][s * 8 + tg]);
                af[mt][1] = __float_as_uint(As[r + g + 8][s * 8 + tg]);
                af[mt][2] = __float_as_uint(As[r + g][s * 8 + tg + 4]);
                af[mt][3] = __float_as_uint(As[r + g + 8][s * 8 + tg + 4]);
            }
#pragma unroll
            for (int nt = 0; nt < 4; nt++) {
                int c = wn + nt * 8 + g;
                unsigned b0 = __float_as_uint(Bs[c][s * 8 + tg]);
                unsigned b1 = __float_as_uint(Bs[c][s * 8 + tg + 4]);
#pragma unroll
                for (int mt = 0; mt < 4; mt++) mma8(cf[mt][nt], af[mt], b0, b1);
            }
        }
    }

#pragma unroll
    for (int mt = 0; mt < 4; mt++) {
        int m = bm + wm + mt * 16 + g;
#pragma unroll
        for (int nt = 0; nt < 4; nt++) {
            int n = bn + wn + nt * 8 + 2 * tg;
            float2 lo = make_float2(cf[mt][nt][0], cf[mt][nt][1]);
            float2 hi = make_float2(cf[mt][nt][2], cf[mt][nt][3]);
            if (mode == 0) {
                *(float2*)&C[(size_t)m * N + n] = lo;
                *(float2*)&C[(size_t)(m + 8) * N + n] = hi;
            } else {
                int h = n >> 6, d = n & 63;
                *(float2*)&C[(size_t)(h * M + m) * 64 + d] = lo;
                *(float2*)&C[(size_t)(h * M + m + 8) * 64 + d] = hi;
            }
        }
    }
}

// ---------------------------------------------------------------------------
// RoPE over first 32 dims of each head (ROT_SCALE = 1)
// ---------------------------------------------------------------------------
__global__ void rope_kernel(float* __restrict__ buf, const float* __restrict__ freqs)
{
    int idx = blockIdx.x * blockDim.x + threadIdx.x;  // NH*T_DIM*16 total
    int p = idx & 15;
    int t = (idx >> 4) & (T_DIM - 1);
    int h = idx >> 16;
    if (h >= NH) return;
    float* x = buf + ((size_t)h * T_DIM + t) * HD;
    float a = x[p];
    float b = x[p + 16];
    float f0 = freqs[t * L_ROT + p];
    float f1 = freqs[t * L_ROT + p + 16];
    x[p]      = a * cosf(f0) - b * sinf(f0);
    x[p + 16] = b * cosf(f1) + a * sinf(f1);
}

// ---------------------------------------------------------------------------
// Flash attention, tf32 mma. Block = 128 threads (4 warps), 64 query rows.
// Warp w owns i-rows [w*16, w*16+16). K tile [j][k] pad 68 (B-frags CF),
// V^T tile [c][j] pad 65, S/P [i][j] pad 69 (softmax + A-frags CF).
// ---------------------------------------------------------------------------
#define KS_PAD 68
#define VS_PAD 65
#define SS_PAD 69
#define ATT_SMEM_FLOATS (64*KS_PAD + 64*VS_PAD + 64*SS_PAD + 64*3 + 128*2)

__global__ __launch_bounds__(128) void attn_mma(
    const float* __restrict__ Qb, const float* __restrict__ Kb,
    const float* __restrict__ Vb, float* __restrict__ vals)
{
    extern __shared__ float sm[];
    float* Ks   = sm;                        // [64][68]
    float* Vs   = Ks + 64 * KS_PAD;          // [64][65]  (V transposed: [c][j])
    float* Ss   = Vs + 64 * VS_PAD;          // [64][69]
    float* mrow = Ss + 64 * SS_PAD;          // [64]
    float* lrow = mrow + 64;                 // [64]
    float* crow = lrow + 64;                 // [64]
    float* pmax = crow + 64;                 // [2][64]
    float* psum = pmax + 128;                // [2][64]

    const int h = blockIdx.y;
    const int it = blockIdx.x;
    const int tid = threadIdx.x;
    const int w = tid >> 5, lane = tid & 31;
    const int g = lane >> 2, tg = lane & 3;
    const int stripe = w * 16;

    // Q fragments in registers, pre-scaled by 1/sqrt(64)=0.125, tf32
    const float* Qh = Qb + ((size_t)h * T_DIM + it * 64) * HD;
    unsigned qf[8][4];
#pragma unroll
    for (int s = 0; s < 8; s++) {
        int r0 = (stripe + g) * HD, r1 = (stripe + g + 8) * HD;
        qf[s][0] = f2tf(Qh[r0 + s * 8 + tg] * 0.125f);
        qf[s][1] = f2tf(Qh[r1 + s * 8 + tg] * 0.125f);
        qf[s][2] = f2tf(Qh[r0 + s * 8 + tg + 4] * 0.125f);
        qf[s][3] = f2tf(Qh[r1 + s * 8 + tg + 4] * 0.125f);
    }

    float of[8][4];
#pragma unroll
    for (int nt = 0; nt < 8; nt++)
#pragma unroll
        for (int r = 0; r < 4; r++) of[nt][r] = 0.f;

    if (tid < 64) { mrow[tid] = -INFINITY; lrow[tid] = 0.f; }

    const float* Kh = Kb + (size_t)h * T_DIM * HD;
    const float* Vh = Vb + (size_t)h * T_DIM * HD;

    const int row = tid & 63, half = tid >> 6;
    const int cbeg = half * 32;

    for (int jt = 0; jt <= it; jt++) {
        __syncthreads();   // (a) prev-iter reads of Ks/Vs/Ss done; mrow init visible
        // --- load K tile (tf32) and V tile transposed (tf32) ---
#pragma unroll
        for (int p = 0; p < 8; p++) {
            int idx = tid + p * 128;
            int j = idx >> 4, c4 = idx & 15;
            float4 kf = *(const float4*)&Kh[(size_t)(jt * 64 + j) * HD + 4 * c4];
            float4 kt = make_float4(__uint_as_float(f2tf(kf.x)), __uint_as_float(f2tf(kf.y)),
                                    __uint_as_float(f2tf(kf.z)), __uint_as_float(f2tf(kf.w)));
            *(float4*)&Ks[j * KS_PAD + 4 * c4] = kt;
            float4 vf = *(const float4*)&Vh[(size_t)(jt * 64 + j) * HD + 4 * c4];
            Vs[(4 * c4 + 0) * VS_PAD + j] = __uint_as_float(f2tf(vf.x));
            Vs[(4 * c4 + 1) * VS_PAD + j] = __uint_as_float(f2tf(vf.y));
            Vs[(4 * c4 + 2) * VS_PAD + j] = __uint_as_float(f2tf(vf.z));
            Vs[(4 * c4 + 3) * VS_PAD + j] = __uint_as_float(f2tf(vf.w));
        }
        __syncthreads();   // (b) tiles ready

        // --- S = Q K^T (already scaled) ---
#pragma unroll
        for (int nt = 0; nt < 8; nt++) {
            float sf[4] = {0.f, 0.f, 0.f, 0.f};
#pragma unroll
            for (int s = 0; s < 8; s++) {
                unsigned b0 = __float_as_uint(Ks[(nt * 8 + g) * KS_PAD + s * 8 + tg]);
                unsigned b1 = __float_as_uint(Ks[(nt * 8 + g) * KS_PAD + s * 8 + tg + 4]);
                mma8(sf, qf[s], b0, b1);
            }
            int r0 = stripe + g, col = nt * 8 + 2 * tg;
            Ss[r0 * SS_PAD + col]           = sf[0];
            Ss[r0 * SS_PAD + col + 1]       = sf[1];
            Ss[(r0 + 8) * SS_PAD + col]     = sf[2];
            Ss[(r0 + 8) * SS_PAD + col + 1] = sf[3];
        }
        __syncthreads();   // (c) S ready

        // --- softmax: 128 threads, half-row each ---
        const int jmaxl = (it - jt) * 64 + row;   // local causal limit (>=63 when jt<it)
        float lmax = -INFINITY;
#pragma unroll
        for (int jj = 0; jj < 32; jj++) {
            int c = cbeg + jj;
            if (c <= jmaxl) lmax = fmaxf(lmax, Ss[row * SS_PAD + c]);
        }
        pmax[half * 64 + row] = lmax;
        __syncthreads();   // (d) partial maxima ready

        float mold = mrow[row];
        float mnew = fmaxf(mold, fmaxf(pmax[row], pmax[64 + row]));
        float corrv = __expf(mold - mnew);
        float ls = 0.f;
#pragma unroll
        for (int jj = 0; jj < 32; jj++) {
            int c = cbeg + jj;
            float p = (c <= jmaxl) ? __expf(Ss[row * SS_PAD + c] - mnew) : 0.f;
            ls += p;
            Ss[row * SS_PAD + c] = __uint_as_float(f2tf(p));
        }
        psum[half * 64 + row] = ls;
        if (half == 0) crow[row] = corrv;
        __syncthreads();   // (e) P, corr, partial sums ready

        if (half == 0) {
            lrow[row] = lrow[row] * corrv + psum[row] + psum[64 + row];
            mrow[row] = mnew;
        }

        // --- rescale O, then O += P V ---
        float cr0 = crow[stripe + g], cr1 = crow[stripe + g + 8];
#pragma unroll
        for (int nt = 0; nt < 8; nt++) {
            of[nt][0] *= cr0; of[nt][1] *= cr0;
            of[nt][2] *= cr1; of[nt][3] *= cr1;
        }
#pragma unroll
        for (int s = 0; s < 8; s++) {
            unsigned af[4];
            af[0] = __float_as_uint(Ss[(stripe + g) * SS_PAD + s * 8 + tg]);
            af[1] = __float_as_uint(Ss[(stripe + g + 8) * SS_PAD + s * 8 + tg]);
            af[2] = __float_as_uint(Ss[(stripe + g) * SS_PAD + s * 8 + tg + 4]);
            af[3] = __float_as_uint(Ss[(stripe + g + 8) * SS_PAD + s * 8 + tg + 4]);
#pragma unroll
            for (int nt = 0; nt < 8; nt++) {
                unsigned b0 = __float_as_uint(Vs[(nt * 8 + g) * VS_PAD + s * 8 + tg]);
                unsigned b1 = __float_as_uint(Vs[(nt * 8 + g) * VS_PAD + s * 8 + tg + 4]);
                mma8(of[nt], af, b0, b1);
            }
        }
    }

    // --- epilogue: O /= l, write [t][h*64+c] ---
    __syncthreads();
    if (tid < 64) crow[tid] = 1.f / lrow[tid];
    __syncthreads();
    float i0 = crow[stripe + g], i1 = crow[stripe + g + 8];
    int qi0 = it * 64 + stripe + g;
#pragma unroll
    for (int nt = 0; nt < 8; nt++) {
        int col = h * 64 + nt * 8 + 2 * tg;
        *(float2*)&vals[(size_t)qi0 * D_DIM + col] =
            make_float2(of[nt][0] * i0, of[nt][1] * i0);
        *(float2*)&vals[(size_t)(qi0 + 8) * D_DIM + col] =
            make_float2(of[nt][2] * i1, of[nt][3] * i1);
    }
}

// ---------------------------------------------------------------------------
extern "C" void kernel_launch(void* const* d_in, const int* in_sizes, int n_in,
                              void* d_out, int out_size)
{
    const float* q     = (const float*)d_in[0];
    const float* k     = (const float*)d_in[1];
    const float* v     = (const float*)d_in[2];
    // d_in[3] = mask (causal, static -> unused)
    const float* freqs = (const float*)d_in[4];
    const float* wq    = (const float*)d_in[5];
    const float* wk    = (const float*)d_in[6];
    const float* wv    = (const float*)d_in[7];
    const float* wo    = (const float*)d_in[8];
    float* out = (float*)d_out;

    float *gq, *gk, *gv, *gvals;
    cudaGetSymbolAddress((void**)&gq, g_Q);
    cudaGetSymbolAddress((void**)&gk, g_K);
    cudaGetSymbolAddress((void**)&gv, g_V);
    cudaGetSymbolAddress((void**)&gvals, g_vals);

    const int att_smem = ATT_SMEM_FLOATS * sizeof(float);  // ~53.5 KB
    cudaFuncSetAttribute(attn_mma, cudaFuncAttributeMaxDynamicSharedMemorySize, att_smem);

    dim3 ggrid(D_DIM / 128, T_DIM / 128);  // (8, 32)

    gemm_tf32<<<ggrid, 256>>>(q, wq, gq, T_DIM, D_DIM, D_DIM, 1);
    gemm_tf32<<<ggrid, 256>>>(k, wk, gk, T_DIM, D_DIM, D_DIM, 1);
    gemm_tf32<<<ggrid, 256>>>(v, wv, gv, T_DIM, D_DIM, D_DIM, 1);

    int rope_threads = NH * T_DIM * 16;
    rope_kernel<<<rope_threads / 256, 256>>>(gq, freqs);
    rope_kernel<<<rope_threads / 256, 256>>>(gk, freqs);
    rope_kernel<<<rope_threads / 256, 256>>>(gv, freqs);

    attn_mma<<<dim3(T_DIM / 64, NH), 128, att_smem>>>(gq, gk, gv, gvals);

    gemm_tf32<<<ggrid, 256>>>(gvals, wo, out, T_DIM, D_DIM, D_DIM, 0);
}